// round 1
// baseline (speedup 1.0000x reference)
#include <cuda_runtime.h>
#include <cstdint>

#define HD 128      // hidden width
#define MT 128      // rows per CTA
#define HS2 129     // float2 stride for activation buffer (pad kills bank conflicts)
#define WS 129      // float stride for transposed weight buffer

// head results: [branch][n in {0,1}] = (v, dv)
__device__ float2 g_head[3][2];

union F2U { float2 f; unsigned long long u; };

__device__ __forceinline__ unsigned long long pack2(float a, float b) {
    unsigned long long r;
    asm("mov.b64 %0, {%1, %2};" : "=l"(r) : "f"(a), "f"(b));
    return r;
}

// ---------------------------------------------------------------------------
// Head kernel: compute (v, dv) for n = 0 and n = 1, all 3 branches.
// One block of 128 threads; W2/W3 staged coalesced into padded SMEM.
// ---------------------------------------------------------------------------
__global__ void head_kernel(const float* __restrict__ t,
    const float* __restrict__ W1, const float* __restrict__ b1,
    const float* __restrict__ W2, const float* __restrict__ b2,
    const float* __restrict__ W3, const float* __restrict__ b3,
    const float* __restrict__ W4, const float* __restrict__ b4)
{
    extern __shared__ float hsm[];          // HD*WS floats (padded W)
    __shared__ float2 A[HD], B[HD];
    __shared__ float2 red[HD];
    const int j = threadIdx.x;
    float tv0 = t[0], tv1 = t[1];

    for (int b = 0; b < 3; ++b) {
        float w1 = W1[b*HD + j];
        float c1 = b1[b*HD + j];
        float c2 = b2[b*HD + j];
        float c3 = b3[b*HD + j];
        float w4 = W4[b*HD + j];
        for (int n = 0; n < 2; ++n) {
            float tn = (n == 0) ? tv0 : tv1;
            float pre = fmaf(tn, w1, c1);
            A[j] = make_float2(fmaxf(pre, 0.f), pre > 0.f ? w1 : 0.f);
            __syncthreads();
            // stage W2 (coalesced read, padded write)
            for (int idx = j; idx < HD*HD; idx += HD) {
                int jj = idx >> 7, k = idx & 127;
                hsm[jj*WS + k] = W2[b*HD*HD + idx];
            }
            __syncthreads();
            {
                float av = 0.f, ad = 0.f;
                #pragma unroll 8
                for (int k = 0; k < HD; ++k) {
                    float w = hsm[j*WS + k]; float2 h = A[k];
                    av = fmaf(w, h.x, av); ad = fmaf(w, h.y, ad);
                }
                float p = av + c2;
                B[j] = make_float2(fmaxf(p, 0.f), p > 0.f ? ad : 0.f);
            }
            __syncthreads();
            for (int idx = j; idx < HD*HD; idx += HD) {
                int jj = idx >> 7, k = idx & 127;
                hsm[jj*WS + k] = W3[b*HD*HD + idx];
            }
            __syncthreads();
            {
                float av = 0.f, ad = 0.f;
                #pragma unroll 8
                for (int k = 0; k < HD; ++k) {
                    float w = hsm[j*WS + k]; float2 h = B[k];
                    av = fmaf(w, h.x, av); ad = fmaf(w, h.y, ad);
                }
                float p = av + c3;
                A[j] = make_float2(fmaxf(p, 0.f), p > 0.f ? ad : 0.f);
            }
            __syncthreads();
            red[j] = make_float2(w4 * A[j].x, w4 * A[j].y);
            __syncthreads();
            for (int s = 64; s > 0; s >>= 1) {
                if (j < s) { red[j].x += red[j+s].x; red[j].y += red[j+s].y; }
                __syncthreads();
            }
            if (j == 0) g_head[b][n] = make_float2(red[0].x + b4[b], red[0].y);
            __syncthreads();
        }
    }
}

// ---------------------------------------------------------------------------
// Main fused kernel
// ---------------------------------------------------------------------------
__device__ __forceinline__ void mm_accum(const float2* __restrict__ sh,
                                         const float* __restrict__ sWt,
                                         const float* __restrict__ sBias,
                                         int rowbase, int colg, F2U (&acc)[8][8])
{
    #pragma unroll
    for (int c = 0; c < 8; ++c) {
        float bv = sBias[colg + 16*c];
        #pragma unroll
        for (int r = 0; r < 8; ++r) acc[r][c].f = make_float2(bv, 0.f);
    }
    #pragma unroll 2
    for (int k = 0; k < HD; ++k) {
        F2U hr[8];
        #pragma unroll
        for (int r = 0; r < 8; ++r) hr[r].f = sh[(rowbase + r)*HS2 + k];
        const float* wrow = sWt + k*WS + colg;
        #pragma unroll
        for (int c = 0; c < 8; ++c) {
            float w = wrow[16*c];
            unsigned long long wp = pack2(w, w);
            #pragma unroll
            for (int r = 0; r < 8; ++r)
                asm("fma.rn.f32x2 %0, %1, %2, %0;"
                    : "+l"(acc[r][c].u) : "l"(wp), "l"(hr[r].u));
        }
    }
}

__device__ __forceinline__ void writeback(float2* __restrict__ sh,
                                          int rowbase, int colg, F2U (&acc)[8][8])
{
    #pragma unroll
    for (int c = 0; c < 8; ++c) {
        int jj = colg + 16*c;
        #pragma unroll
        for (int r = 0; r < 8; ++r) {
            float pv = acc[r][c].f.x;
            sh[(rowbase + r)*HS2 + jj] =
                make_float2(fmaxf(pv, 0.f), pv > 0.f ? acc[r][c].f.y : 0.f);
        }
    }
}

__global__ __launch_bounds__(256, 1)
void main_kernel(const float* __restrict__ t,
    const float* __restrict__ W1, const float* __restrict__ b1,
    const float* __restrict__ W2, const float* __restrict__ b2,
    const float* __restrict__ W3, const float* __restrict__ b3,
    const float* __restrict__ W4, const float* __restrict__ b4,
    float* __restrict__ out, int N)
{
    extern __shared__ float smem[];
    float2* sh    = (float2*)smem;                  // MT*HS2 float2
    float*  sWt   = smem + MT*HS2*2;                // HD*WS
    float*  sW1   = sWt + HD*WS;
    float*  sB1   = sW1 + HD;
    float*  sBias = sB1 + HD;
    float*  sW4   = sBias + HD;
    float*  sT    = sW4 + HD;                       // MT
    float2* red   = (float2*)(sT + MT);             // 256 float2

    const int tid = threadIdx.x;
    const int base = blockIdx.x * MT;
    const int rowbase = (tid >> 4) * 8;
    const int colg = tid & 15;

    if (tid < MT) sT[tid] = t[base + tid];

    for (int b = 0; b < 3; ++b) {
        // P0: stage w1/b1/b2 + W2^T
        if (tid < HD) {
            sW1[tid]   = W1[b*HD + tid];
            sB1[tid]   = b1[b*HD + tid];
            sBias[tid] = b2[b*HD + tid];
        }
        {
            const float* Wb = W2 + b*HD*HD;
            #pragma unroll 4
            for (int idx = tid; idx < HD*HD; idx += 256) {
                int jj = idx >> 7, k = idx & 127;
                sWt[k*WS + jj] = Wb[idx];
            }
        }
        __syncthreads();

        // P1: layer 1 (elementwise)
        #pragma unroll 4
        for (int idx = tid; idx < MT*HD; idx += 256) {
            int r = idx >> 7, jj = idx & 127;
            float w = sW1[jj];
            float pre = fmaf(sT[r], w, sB1[jj]);
            sh[r*HS2 + jj] = make_float2(fmaxf(pre, 0.f), pre > 0.f ? w : 0.f);
        }
        __syncthreads();

        F2U acc[8][8];
        // layer 2
        mm_accum(sh, sWt, sBias, rowbase, colg, acc);
        __syncthreads();
        // P3: writeback h2 + stage W3^T/b3
        writeback(sh, rowbase, colg, acc);
        {
            const float* Wb = W3 + b*HD*HD;
            #pragma unroll 4
            for (int idx = tid; idx < HD*HD; idx += 256) {
                int jj = idx >> 7, k = idx & 127;
                sWt[k*WS + jj] = Wb[idx];
            }
        }
        if (tid < HD) sBias[tid] = b3[b*HD + tid];
        __syncthreads();

        // layer 3
        mm_accum(sh, sWt, sBias, rowbase, colg, acc);
        __syncthreads();
        // P5: writeback h3 + stage w4
        writeback(sh, rowbase, colg, acc);
        if (tid < HD) sW4[tid] = W4[b*HD + tid];
        __syncthreads();

        // P6: layer 4 partial dots (2 threads per row)
        {
            int row = tid & 127;
            int j0 = (tid >> 7) * 64;
            float sv = 0.f, sd = 0.f;
            #pragma unroll 8
            for (int j = j0; j < j0 + 64; ++j) {
                float w = sW4[j];
                float2 h = sh[row*HS2 + j];
                sv = fmaf(w, h.x, sv);
                sd = fmaf(w, h.y, sd);
            }
            red[tid] = make_float2(sv, sd);
        }
        __syncthreads();

        // P7: finalize + post-process + store
        if (tid < MT) {
            float v  = red[tid].x + red[tid + 128].x + b4[b];
            float dv = red[tid].y + red[tid + 128].y;
            float2 h0 = g_head[b][0];
            float2 h1 = g_head[b][1];
            float s = (b == 1) ? -1.f : 1.f;
            float d1 = h1.x - h0.x;
            float sg1 = (d1 > 0.f) ? 1.f : ((d1 < 0.f) ? -1.f : 0.f);
            float dsign1 = s * sg1 * h1.y;
            int n = base + tid;
            float d = v - h0.x;
            float vv, ds;
            if (n == 0) {
                vv = 0.f;
                ds = (dsign1 >= 0.f) ? fabsf(dv) : -fabsf(dv);
            } else {
                float sg = (d > 0.f) ? 1.f : ((d < 0.f) ? -1.f : 0.f);
                vv = s * fabsf(d);
                ds = s * sg * dv;
            }
            out[b*N + n]       = vv;   // alpha / xp / yp
            out[(3 + b)*N + n] = ds;   // da / dx / dy
        }
        __syncthreads();
    }
}

// ---------------------------------------------------------------------------
extern "C" void kernel_launch(void* const* d_in, const int* in_sizes, int n_in,
                              void* d_out, int out_size)
{
    const float* t  = (const float*)d_in[0];
    const float* W1 = (const float*)d_in[1];
    const float* b1 = (const float*)d_in[2];
    const float* W2 = (const float*)d_in[3];
    const float* b2 = (const float*)d_in[4];
    const float* W3 = (const float*)d_in[5];
    const float* b3 = (const float*)d_in[6];
    const float* W4 = (const float*)d_in[7];
    const float* b4 = (const float*)d_in[8];
    float* out = (float*)d_out;
    const int N = in_sizes[0];

    const int MAIN_SMEM = (MT*HS2*2 + HD*WS + 4*HD + MT + 512) * 4; // bytes
    const int HEAD_SMEM = HD*WS*4;

    cudaFuncSetAttribute(main_kernel, cudaFuncAttributeMaxDynamicSharedMemorySize, MAIN_SMEM);
    cudaFuncSetAttribute(head_kernel, cudaFuncAttributeMaxDynamicSharedMemorySize, HEAD_SMEM);

    head_kernel<<<1, HD, HEAD_SMEM>>>(t, W1, b1, W2, b2, W3, b3, W4, b4);
    main_kernel<<<N / MT, 256, MAIN_SMEM>>>(t, W1, b1, W2, b2, W3, b3, W4, b4, out, N);
}

// round 2
// speedup vs baseline: 1.0315x; 1.0315x over previous
#include <cuda_runtime.h>
#include <cstdint>

#define HD 128      // hidden width
#define MT 128      // rows per CTA
#define HS2 129     // float2 stride for activation buffer (pad kills bank conflicts)
#define WS 129      // float stride for transposed weight buffer
#define NT 512      // threads per CTA
#define RPT 4       // rows per thread (MT / (NT/16))

// head results: [branch][n in {0,1}] = (v, dv)
__device__ float2 g_head[3][2];

union F2U { float2 f; unsigned long long u; };

__device__ __forceinline__ unsigned long long pack2(float a, float b) {
    unsigned long long r;
    asm("mov.b64 %0, {%1, %2};" : "=l"(r) : "f"(a), "f"(b));
    return r;
}

// ---------------------------------------------------------------------------
// Head kernel: compute (v, dv) for n = 0 and n = 1, all 3 branches.
// ---------------------------------------------------------------------------
__global__ void head_kernel(const float* __restrict__ t,
    const float* __restrict__ W1, const float* __restrict__ b1,
    const float* __restrict__ W2, const float* __restrict__ b2,
    const float* __restrict__ W3, const float* __restrict__ b3,
    const float* __restrict__ W4, const float* __restrict__ b4)
{
    extern __shared__ float hsm[];          // HD*WS floats (padded W)
    __shared__ float2 A[HD], B[HD];
    __shared__ float2 red[HD];
    const int j = threadIdx.x;
    float tv0 = t[0], tv1 = t[1];

    for (int b = 0; b < 3; ++b) {
        float w1 = W1[b*HD + j];
        float c1 = b1[b*HD + j];
        float c2 = b2[b*HD + j];
        float c3 = b3[b*HD + j];
        float w4 = W4[b*HD + j];
        for (int n = 0; n < 2; ++n) {
            float tn = (n == 0) ? tv0 : tv1;
            float pre = fmaf(tn, w1, c1);
            A[j] = make_float2(fmaxf(pre, 0.f), pre > 0.f ? w1 : 0.f);
            __syncthreads();
            for (int idx = j; idx < HD*HD; idx += HD) {
                int jj = idx >> 7, k = idx & 127;
                hsm[jj*WS + k] = W2[b*HD*HD + idx];
            }
            __syncthreads();
            {
                float av = 0.f, ad = 0.f;
                #pragma unroll 8
                for (int k = 0; k < HD; ++k) {
                    float w = hsm[j*WS + k]; float2 h = A[k];
                    av = fmaf(w, h.x, av); ad = fmaf(w, h.y, ad);
                }
                float p = av + c2;
                B[j] = make_float2(fmaxf(p, 0.f), p > 0.f ? ad : 0.f);
            }
            __syncthreads();
            for (int idx = j; idx < HD*HD; idx += HD) {
                int jj = idx >> 7, k = idx & 127;
                hsm[jj*WS + k] = W3[b*HD*HD + idx];
            }
            __syncthreads();
            {
                float av = 0.f, ad = 0.f;
                #pragma unroll 8
                for (int k = 0; k < HD; ++k) {
                    float w = hsm[j*WS + k]; float2 h = B[k];
                    av = fmaf(w, h.x, av); ad = fmaf(w, h.y, ad);
                }
                float p = av + c3;
                A[j] = make_float2(fmaxf(p, 0.f), p > 0.f ? ad : 0.f);
            }
            __syncthreads();
            red[j] = make_float2(w4 * A[j].x, w4 * A[j].y);
            __syncthreads();
            for (int s = 64; s > 0; s >>= 1) {
                if (j < s) { red[j].x += red[j+s].x; red[j].y += red[j+s].y; }
                __syncthreads();
            }
            if (j == 0) g_head[b][n] = make_float2(red[0].x + b4[b], red[0].y);
            __syncthreads();
        }
    }
}

// ---------------------------------------------------------------------------
// Main fused kernel
// ---------------------------------------------------------------------------
__device__ __forceinline__ void mm_accum(const float2* __restrict__ sh,
                                         const float* __restrict__ sWt,
                                         const float* __restrict__ sBias,
                                         int rowbase, int colg, F2U (&acc)[RPT][8])
{
    #pragma unroll
    for (int c = 0; c < 8; ++c) {
        float bv = sBias[colg + 16*c];
        #pragma unroll
        for (int r = 0; r < RPT; ++r) acc[r][c].f = make_float2(bv, 0.f);
    }
    #pragma unroll 2
    for (int k = 0; k < HD; ++k) {
        F2U hr[RPT];
        #pragma unroll
        for (int r = 0; r < RPT; ++r) hr[r].f = sh[(rowbase + r)*HS2 + k];
        const float* wrow = sWt + k*WS + colg;
        #pragma unroll
        for (int c = 0; c < 8; ++c) {
            float w = wrow[16*c];
            unsigned long long wp = pack2(w, w);
            #pragma unroll
            for (int r = 0; r < RPT; ++r)
                asm("fma.rn.f32x2 %0, %1, %2, %0;"
                    : "+l"(acc[r][c].u) : "l"(wp), "l"(hr[r].u));
        }
    }
}

__device__ __forceinline__ void writeback(float2* __restrict__ sh,
                                          int rowbase, int colg, F2U (&acc)[RPT][8])
{
    #pragma unroll
    for (int c = 0; c < 8; ++c) {
        int jj = colg + 16*c;
        #pragma unroll
        for (int r = 0; r < RPT; ++r) {
            float pv = acc[r][c].f.x;
            sh[(rowbase + r)*HS2 + jj] =
                make_float2(fmaxf(pv, 0.f), pv > 0.f ? acc[r][c].f.y : 0.f);
        }
    }
}

__global__ __launch_bounds__(NT, 1)
void main_kernel(const float* __restrict__ t,
    const float* __restrict__ W1, const float* __restrict__ b1,
    const float* __restrict__ W2, const float* __restrict__ b2,
    const float* __restrict__ W3, const float* __restrict__ b3,
    const float* __restrict__ W4, const float* __restrict__ b4,
    float* __restrict__ out, int N)
{
    extern __shared__ float smem[];
    float2* sh    = (float2*)smem;                  // MT*HS2 float2
    float*  sWt   = smem + MT*HS2*2;                // HD*WS
    float*  sW1   = sWt + HD*WS;
    float*  sB1   = sW1 + HD;
    float*  sBias = sB1 + HD;
    float*  sW4   = sBias + HD;
    float*  sT    = sW4 + HD;                       // MT
    float2* red   = (float2*)(sT + MT);             // NT float2

    const int tid = threadIdx.x;
    const int base = blockIdx.x * MT;
    const int rowbase = (tid >> 4) * RPT;
    const int colg = tid & 15;

    if (tid < MT) sT[tid] = t[base + tid];

    for (int b = 0; b < 3; ++b) {
        // P0: stage w1/b1/b2 + W2^T
        if (tid < HD) {
            sW1[tid]   = W1[b*HD + tid];
            sB1[tid]   = b1[b*HD + tid];
            sBias[tid] = b2[b*HD + tid];
        }
        {
            const float* Wb = W2 + b*HD*HD;
            #pragma unroll 4
            for (int idx = tid; idx < HD*HD; idx += NT) {
                int jj = idx >> 7, k = idx & 127;
                sWt[k*WS + jj] = Wb[idx];
            }
        }
        __syncthreads();

        // P1: layer 1 (elementwise)
        #pragma unroll 4
        for (int idx = tid; idx < MT*HD; idx += NT) {
            int r = idx >> 7, jj = idx & 127;
            float w = sW1[jj];
            float pre = fmaf(sT[r], w, sB1[jj]);
            sh[r*HS2 + jj] = make_float2(fmaxf(pre, 0.f), pre > 0.f ? w : 0.f);
        }
        __syncthreads();

        F2U acc[RPT][8];
        // layer 2
        mm_accum(sh, sWt, sBias, rowbase, colg, acc);
        __syncthreads();
        // P3: writeback h2 + stage W3^T/b3
        writeback(sh, rowbase, colg, acc);
        {
            const float* Wb = W3 + b*HD*HD;
            #pragma unroll 4
            for (int idx = tid; idx < HD*HD; idx += NT) {
                int jj = idx >> 7, k = idx & 127;
                sWt[k*WS + jj] = Wb[idx];
            }
        }
        if (tid < HD) sBias[tid] = b3[b*HD + tid];
        __syncthreads();

        // layer 3
        mm_accum(sh, sWt, sBias, rowbase, colg, acc);
        __syncthreads();
        // P5: writeback h3 + stage w4
        writeback(sh, rowbase, colg, acc);
        if (tid < HD) sW4[tid] = W4[b*HD + tid];
        __syncthreads();

        // P6: layer 4 partial dots (4 threads per row, 32 cols each)
        {
            int row = tid & 127;
            int j0 = (tid >> 7) * 32;
            float sv = 0.f, sd = 0.f;
            #pragma unroll 8
            for (int j = j0; j < j0 + 32; ++j) {
                float w = sW4[j];
                float2 h = sh[row*HS2 + j];
                sv = fmaf(w, h.x, sv);
                sd = fmaf(w, h.y, sd);
            }
            red[tid] = make_float2(sv, sd);
        }
        __syncthreads();

        // P7: finalize + post-process + store
        if (tid < MT) {
            float v  = red[tid].x + red[tid + 128].x + red[tid + 256].x + red[tid + 384].x + b4[b];
            float dv = red[tid].y + red[tid + 128].y + red[tid + 256].y + red[tid + 384].y;
            float2 h0 = g_head[b][0];
            float2 h1 = g_head[b][1];
            float s = (b == 1) ? -1.f : 1.f;
            float d1 = h1.x - h0.x;
            float sg1 = (d1 > 0.f) ? 1.f : ((d1 < 0.f) ? -1.f : 0.f);
            float dsign1 = s * sg1 * h1.y;
            int n = base + tid;
            float d = v - h0.x;
            float vv, ds;
            if (n == 0) {
                vv = 0.f;
                ds = (dsign1 >= 0.f) ? fabsf(dv) : -fabsf(dv);
            } else {
                float sg = (d > 0.f) ? 1.f : ((d < 0.f) ? -1.f : 0.f);
                vv = s * fabsf(d);
                ds = s * sg * dv;
            }
            out[b*N + n]       = vv;   // alpha / xp / yp
            out[(3 + b)*N + n] = ds;   // da / dx / dy
        }
        __syncthreads();
    }
}

// ---------------------------------------------------------------------------
extern "C" void kernel_launch(void* const* d_in, const int* in_sizes, int n_in,
                              void* d_out, int out_size)
{
    const float* t  = (const float*)d_in[0];
    const float* W1 = (const float*)d_in[1];
    const float* b1 = (const float*)d_in[2];
    const float* W2 = (const float*)d_in[3];
    const float* b2 = (const float*)d_in[4];
    const float* W3 = (const float*)d_in[5];
    const float* b3 = (const float*)d_in[6];
    const float* W4 = (const float*)d_in[7];
    const float* b4 = (const float*)d_in[8];
    float* out = (float*)d_out;
    const int N = in_sizes[0];

    const int MAIN_SMEM = (MT*HS2*2 + HD*WS + 4*HD + MT + 2*NT + 64) * 4; // bytes
    const int HEAD_SMEM = HD*WS*4;

    cudaFuncSetAttribute(main_kernel, cudaFuncAttributeMaxDynamicSharedMemorySize, MAIN_SMEM);
    cudaFuncSetAttribute(head_kernel, cudaFuncAttributeMaxDynamicSharedMemorySize, HEAD_SMEM);

    head_kernel<<<1, HD, HEAD_SMEM>>>(t, W1, b1, W2, b2, W3, b3, W4, b4);
    main_kernel<<<N / MT, NT, MAIN_SMEM>>>(t, W1, b1, W2, b2, W3, b3, W4, b4, out, N);
}